// round 16
// baseline (speedup 1.0000x reference)
#include <cuda_runtime.h>
#include <cuda_fp16.h>
#include <math.h>
#include <stdint.h>

#define TWO_B 32768
#define B_HALF 16384
#define DIM 256
#define KC 1024
#define BM 128
#define BN 128
#define TOFF2 43.2800875f     // 30 * log2(e)
#define TS2   28.8539008f     // 20 * log2(e)
#define SSH   12.0f
#define LN2   0.6931471805599453f

// ---------------- device scratch (static, no allocation) ----------------
__device__ __align__(16) int8_t g_zq[(size_t)TWO_B * DIM];
__device__ __align__(16) int8_t g_pq[(size_t)TWO_B * DIM];
__device__ __align__(16) int8_t g_cq[(size_t)KC * DIM];
__device__ float g_rsz[TWO_B];
__device__ float g_rsp[TWO_B];
__device__ float g_rsc[KC];
__device__ float g_nz[TWO_B];
__device__ float g_np[TWO_B];
__device__ float g_nc[KC];
__device__ __align__(16) __half g_tz[(size_t)TWO_B * KC];   // z: E = 2^(t2-TOFF2)
__device__ __align__(16) __half g_tp[(size_t)TWO_B * KC];   // p: t2 (log2 domain)
__device__ float g_cs[4 * KC];
__device__ __align__(16) __half g_ih[2 * KC];               // z: 1024/cs
__device__ __align__(16) __half g_lch[2 * KC];              // p: log2(cs)+TOFF2-SSH
__device__ double g_loss;
__device__ unsigned g_done;
__device__ unsigned g_gdone;

// ---------------- PTX helpers ----------------
__device__ __forceinline__ uint32_t smem_u32(const void* p) {
    uint32_t a;
    asm("{ .reg .u64 t; cvta.to.shared.u64 t, %1; cvt.u32.u64 %0, t; }" : "=r"(a) : "l"(p));
    return a;
}
#define CP_ASYNC16(dst, src) \
    asm volatile("cp.async.cg.shared.global [%0], [%1], 16;" :: "r"(dst), "l"(src) : "memory")
#define CP_COMMIT() asm volatile("cp.async.commit_group;" ::: "memory")
#define CP_WAIT(n)  asm volatile("cp.async.wait_group %0;" :: "n"(n) : "memory")
#define LDSM_X4(r0, r1, r2, r3, addr) \
    asm volatile("ldmatrix.sync.aligned.m8n8.x4.shared.b16 {%0,%1,%2,%3}, [%4];" \
                 : "=r"(r0), "=r"(r1), "=r"(r2), "=r"(r3) : "r"(addr))

__device__ __forceinline__ void mma_s8(int* c, const uint32_t* a, const uint32_t* b) {
    asm volatile(
        "mma.sync.aligned.m16n8k32.row.col.s32.s8.s8.s32 "
        "{%0,%1,%2,%3}, {%4,%5,%6,%7}, {%8,%9}, {%0,%1,%2,%3};"
        : "+r"(c[0]), "+r"(c[1]), "+r"(c[2]), "+r"(c[3])
        : "r"(a[0]), "r"(a[1]), "r"(a[2]), "r"(a[3]), "r"(b[0]), "r"(b[1]));
}

__device__ __forceinline__ __half2 h2ex2(__half2 x) {
    uint32_t xi = *reinterpret_cast<uint32_t*>(&x), ri;
    asm("ex2.approx.f16x2 %0, %1;" : "=r"(ri) : "r"(xi));
    return *reinterpret_cast<__half2*>(&ri);
}
__device__ __forceinline__ __half2 h2of(uint32_t u) {
    return *reinterpret_cast<__half2*>(&u);
}
__device__ __forceinline__ uint32_t uof(__half2 h) {
    return *reinterpret_cast<uint32_t*>(&h);
}

__device__ __forceinline__ float dist2f(float sq) {
    return TS2 * sqrtf(fmaxf(sq, 1e-12f));
}

// ---------------- normalize + quantize (+ zero fold-in) ----------------
__device__ __forceinline__ void norm_row_q(const float* __restrict__ src,
                                           int8_t* __restrict__ dstq,
                                           float* __restrict__ rs,
                                           float* __restrict__ nsq, int r, int lane) {
    const float4* s4 = reinterpret_cast<const float4*>(src + (size_t)r * DIM);
    float4 v0 = s4[lane * 2];
    float4 v1 = s4[lane * 2 + 1];
    float ss = v0.x * v0.x + v0.y * v0.y + v0.z * v0.z + v0.w * v0.w
             + v1.x * v1.x + v1.y * v1.y + v1.z * v1.z + v1.w * v1.w;
    #pragma unroll
    for (int o = 16; o > 0; o >>= 1)
        ss += __shfl_xor_sync(0xffffffffu, ss, o);
    float inv = 1.0f / fmaxf(sqrtf(ss), 1e-12f);

    float x[8] = {v0.x * inv, v0.y * inv, v0.z * inv, v0.w * inv,
                  v1.x * inv, v1.y * inv, v1.z * inv, v1.w * inv};
    float m = 0.f;
    #pragma unroll
    for (int j = 0; j < 8; j++) m = fmaxf(m, fabsf(x[j]));
    #pragma unroll
    for (int o = 16; o > 0; o >>= 1)
        m = fmaxf(m, __shfl_xor_sync(0xffffffffu, m, o));

    float s = 127.0f / m;
    int q[8];
    #pragma unroll
    for (int j = 0; j < 8; j++) q[j] = __float2int_rn(x[j] * s);
    uint32_t lo = (q[0] & 0xff) | ((q[1] & 0xff) << 8) | ((q[2] & 0xff) << 16) | ((q[3] & 0xff) << 24);
    uint32_t hi = (q[4] & 0xff) | ((q[5] & 0xff) << 8) | ((q[6] & 0xff) << 16) | ((q[7] & 0xff) << 24);
    *reinterpret_cast<uint2*>(dstq + (size_t)r * DIM + lane * 8) = make_uint2(lo, hi);
    if (lane == 0) {
        rs[r] = m * (1.0f / 127.0f);
        nsq[r] = ss * inv * inv;
    }
}

__global__ __launch_bounds__(256) void normalize_kernel(const float* __restrict__ z,
                                                        const float* __restrict__ p,
                                                        const float* __restrict__ c) {
    if (blockIdx.x == 0) {
        int t = threadIdx.x;
        #pragma unroll
        for (int j = 0; j < 16; j++) g_cs[t + j * 256] = 0.0f;
        if (t == 0) { g_loss = 0.0; g_done = 0u; g_gdone = 0u; }
    }
    int row = blockIdx.x * 8 + (threadIdx.x >> 5);
    int lane = threadIdx.x & 31;
    if (row < TWO_B)          norm_row_q(z, g_zq, g_rsz, g_nz, row, lane);
    else if (row < 2 * TWO_B) norm_row_q(p, g_pq, g_rsp, g_np, row - TWO_B, lane);
    else                      norm_row_q(c, g_cq, g_rsc, g_nc, row - 2 * TWO_B, lane);
}

// ---------------- int8 IMMA GEMM + fused distance/exp epilogue ----------------
#define ROWB 272
#define TILE_BYTES (128 * ROWB)
#define SMEM_TOTAL (2 * TILE_BYTES)
#define NGEMM_BLOCKS 4096

__global__ __launch_bounds__(512, 2) void gemm_dist_imma() {
    extern __shared__ char dsm[];
    uint32_t sA = smem_u32(dsm);
    uint32_t sB = sA + TILE_BYTES;
    __shared__ unsigned s_last;

    int tid = threadIdx.x;
    int lane = tid & 31;
    int wid = tid >> 5;
    int wm = wid >> 2;
    int wn = wid & 3;
    int q = lane & 3;
    int gr = lane >> 2;

    int which = blockIdx.z;
    int bm = blockIdx.y;
    int bn = blockIdx.x;

    const int8_t* Ag = (which ? g_pq : g_zq) + (size_t)(bm * BM) * DIM;
    const int8_t* Bg = g_cq + (size_t)(bn * BN) * DIM;
    const float* na = which ? g_np : g_nz;
    const float* rsa = which ? g_rsp : g_rsz;
    __half* T = which ? g_tp : g_tz;

    int ltile = tid >> 8;
    int local = tid & 255;
    int lrow = local >> 1;
    int lhalf = local & 1;
    const int8_t* gsrc = (ltile ? Bg : Ag) + (size_t)lrow * DIM + lhalf * 128;
    uint32_t sdst = (ltile ? sB : sA) + lrow * ROWB + lhalf * 128;

    #pragma unroll
    for (int c2 = 0; c2 < 8; c2++)
        CP_ASYNC16(sdst + c2 * 16, gsrc + c2 * 16);
    CP_COMMIT();

    int acc[2][4][4];
    #pragma unroll
    for (int i = 0; i < 2; i++)
        #pragma unroll
        for (int j = 0; j < 4; j++)
            #pragma unroll
            for (int k = 0; k < 4; k++)
                acc[i][j][k] = 0;

    uint32_t aBase = sA + (wm * 32 + (lane & 15)) * ROWB + (lane >> 4) * 16;
    uint32_t bBase = sB + (wn * 32 + (lane & 7) + ((lane >> 4) << 3)) * ROWB
                     + ((lane >> 3) & 1) * 16;

    CP_WAIT(0);
    __syncthreads();

    #pragma unroll
    for (int k32 = 0; k32 < 8; k32++) {
        uint32_t a[2][4], b[2][4];
        #pragma unroll
        for (int mt = 0; mt < 2; mt++)
            LDSM_X4(a[mt][0], a[mt][1], a[mt][2], a[mt][3],
                    aBase + mt * (16 * ROWB) + k32 * 32);
        #pragma unroll
        for (int j = 0; j < 2; j++)
            LDSM_X4(b[j][0], b[j][1], b[j][2], b[j][3],
                    bBase + j * (16 * ROWB) + k32 * 32);
        #pragma unroll
        for (int mt = 0; mt < 2; mt++)
            #pragma unroll
            for (int nt = 0; nt < 4; nt++)
                mma_s8(acc[mt][nt], a[mt], &b[nt >> 1][(nt & 1) * 2]);
    }

    // ---------------- epilogue (R15 structure) ----------------
    const __half2 toffh = __float2half2_rn(TOFF2);
    float nc0v[4], nc1v[4], rb0[4], rb1[4];
    #pragma unroll
    for (int nt = 0; nt < 4; nt++) {
        int c = bn * BN + wn * 32 + nt * 8 + 2 * q;
        nc0v[nt] = g_nc[c];
        nc1v[nt] = g_nc[c + 1];
        rb0[nt] = g_rsc[c];
        rb1[nt] = g_rsc[c + 1];
    }

    float es0[4], es1[4];
    #pragma unroll
    for (int nt = 0; nt < 4; nt++) { es0[nt] = 0.f; es1[nt] = 0.f; }

    #pragma unroll
    for (int mt = 0; mt < 2; mt++) {
        int r = bm * BM + wm * 32 + mt * 16 + gr;
        float na0 = na[r], na1 = na[r + 8];
        float ra0 = rsa[r], ra1 = rsa[r + 8];
        #pragma unroll
        for (int nt = 0; nt < 4; nt++) {
            int c = bn * BN + wn * 32 + nt * 8 + 2 * q;
            float g00 = (float)acc[mt][nt][0] * (ra0 * rb0[nt]);
            float g01 = (float)acc[mt][nt][1] * (ra0 * rb1[nt]);
            float g10 = (float)acc[mt][nt][2] * (ra1 * rb0[nt]);
            float g11 = (float)acc[mt][nt][3] * (ra1 * rb1[nt]);
            float t00 = dist2f(na0 + nc0v[nt] - 2.0f * g00);
            float t01 = dist2f(na0 + nc1v[nt] - 2.0f * g01);
            float t10 = dist2f(na1 + nc0v[nt] - 2.0f * g10);
            float t11 = dist2f(na1 + nc1v[nt] - 2.0f * g11);
            __half2 ht0 = __floats2half2_rn(t00, t01);
            __half2 ht1 = __floats2half2_rn(t10, t11);
            __half2 he0 = h2ex2(__hsub2(ht0, toffh));
            __half2 he1 = h2ex2(__hsub2(ht1, toffh));
            *(__half2*)&T[(size_t)r * KC + c]       = which ? ht0 : he0;
            *(__half2*)&T[(size_t)(r + 8) * KC + c] = which ? ht1 : he1;
            float2 f0 = __half22float2(he0);
            float2 f1 = __half22float2(he1);
            es0[nt] += f0.x + f1.x;
            es1[nt] += f0.y + f1.y;
        }
    }

    #pragma unroll
    for (int o = 4; o <= 16; o <<= 1) {
        #pragma unroll
        for (int nt = 0; nt < 4; nt++) {
            es0[nt] += __shfl_xor_sync(0xffffffffu, es0[nt], o);
            es1[nt] += __shfl_xor_sync(0xffffffffu, es1[nt], o);
        }
    }
    if (lane < 4) {
        int csbase = (which * 2 + (bm >> 7)) * KC + bn * BN + wn * 32 + 2 * lane;
        #pragma unroll
        for (int nt = 0; nt < 4; nt++) {
            atomicAdd(&g_cs[csbase + nt * 8], es0[nt]);
            atomicAdd(&g_cs[csbase + nt * 8 + 1], es1[nt]);
        }
    }

    // ---- last block computes the colsum transforms (logcs folded in) ----
    __syncthreads();
    if (tid == 0) {
        __threadfence();
        s_last = (atomicAdd(&g_gdone, 1u) == (unsigned)(NGEMM_BLOCKS - 1));
    }
    __syncthreads();
    if (s_last) {
        for (int i = tid; i < 2 * KC; i += 512)
            g_ih[i] = __float2half(1024.0f / g_cs[i]);
        for (int i = tid; i < 2 * KC; i += 512)
            g_lch[i] = __float2half(log2f(g_cs[2 * KC + i]) + (TOFF2 - SSH));
    }
}

// ---------------- final pass (packed half2 reductions) ----------------
__global__ __launch_bounds__(128) void final_kernel(float* __restrict__ out) {
    __shared__ uint32_t smu[12];
    int b = blockIdx.x;
    int t = threadIdx.x;
    int lane = t & 31;
    int wid = t >> 5;
    int k0 = t * 8;

    uint4 ez1 = *(const uint4*)(g_tz + (size_t)b * KC + k0);
    uint4 ez2 = *(const uint4*)(g_tz + (size_t)(b + B_HALF) * KC + k0);
    uint4 tq1 = *(const uint4*)(g_tp + (size_t)b * KC + k0);
    uint4 tq2 = *(const uint4*)(g_tp + (size_t)(b + B_HALF) * KC + k0);
    uint4 i1u = *(const uint4*)(g_ih + k0);
    uint4 i2u = *(const uint4*)(g_ih + KC + k0);
    uint4 l3u = *(const uint4*)(g_lch + k0);
    uint4 l4u = *(const uint4*)(g_lch + KC + k0);

    const uint32_t* e1w = reinterpret_cast<const uint32_t*>(&ez1);
    const uint32_t* e2w = reinterpret_cast<const uint32_t*>(&ez2);
    const uint32_t* t1w = reinterpret_cast<const uint32_t*>(&tq1);
    const uint32_t* t2w = reinterpret_cast<const uint32_t*>(&tq2);
    const uint32_t* i1w = reinterpret_cast<const uint32_t*>(&i1u);
    const uint32_t* i2w = reinterpret_cast<const uint32_t*>(&i2u);
    const uint32_t* l3w = reinterpret_cast<const uint32_t*>(&l3u);
    const uint32_t* l4w = reinterpret_cast<const uint32_t*>(&l4u);

    __half2 az1h = __float2half2_rn(0.f), az2h = az1h;
    __half2 ap1h = az1h, ap2h = az1h;
    __half2 s1h = az1h, s2h = az1h;

    #pragma unroll
    for (int j = 0; j < 4; j++) {
        __half2 a1 = __hmul2(h2of(e1w[j]), h2of(i1w[j]));
        __half2 a2 = __hmul2(h2of(e2w[j]), h2of(i2w[j]));
        __half2 v1 = __hsub2(h2of(t1w[j]), h2of(l3w[j]));
        __half2 v2 = __hsub2(h2of(t2w[j]), h2of(l4w[j]));
        __half2 p1 = h2ex2(v1);
        __half2 p2 = h2ex2(v2);
        __half2 lp = __hadd2(v1, v2);
        az1h = __hadd2(az1h, a1);
        az2h = __hadd2(az2h, a2);
        ap1h = __hadd2(ap1h, p1);
        ap2h = __hadd2(ap2h, p2);
        s1h = __hfma2(a1, lp, s1h);
        s2h = __hfma2(a2, lp, s2h);
    }

    // collapse element lanes, pack pairs: (az1|az2), (ap1|ap2), (s1|s2)
    __half2 paz = __halves2half2(__hadd(__low2half(az1h), __high2half(az1h)),
                                 __hadd(__low2half(az2h), __high2half(az2h)));
    __half2 pap = __halves2half2(__hadd(__low2half(ap1h), __high2half(ap1h)),
                                 __hadd(__low2half(ap2h), __high2half(ap2h)));
    __half2 ps  = __halves2half2(__hadd(__low2half(s1h), __high2half(s1h)),
                                 __hadd(__low2half(s2h), __high2half(s2h)));

    #pragma unroll
    for (int o = 16; o > 0; o >>= 1) {
        paz = __hadd2(paz, h2of(__shfl_xor_sync(0xffffffffu, uof(paz), o)));
        pap = __hadd2(pap, h2of(__shfl_xor_sync(0xffffffffu, uof(pap), o)));
        ps  = __hadd2(ps,  h2of(__shfl_xor_sync(0xffffffffu, uof(ps), o)));
    }
    if (lane == 0) {
        smu[wid * 3 + 0] = uof(paz);
        smu[wid * 3 + 1] = uof(pap);
        smu[wid * 3 + 2] = uof(ps);
    }
    __syncthreads();
    if (t == 0) {
        float raz1 = 0.f, raz2 = 0.f, rap1 = 0.f, rap2 = 0.f, rs1 = 0.f, rs2 = 0.f;
        #pragma unroll
        for (int w = 0; w < 4; w++) {
            float2 a = __half22float2(h2of(smu[w * 3 + 0]));
            float2 p = __half22float2(h2of(smu[w * 3 + 1]));
            float2 s = __half22float2(h2of(smu[w * 3 + 2]));
            raz1 += a.x; raz2 += a.y;
            rap1 += p.x; rap2 += p.y;
            rs1 += s.x;  rs2 += s.y;
        }
        float lrr = log2f(rap1) + log2f(rap2);
        float dot = (rs1 - lrr * raz1) / raz1 + (rs2 - lrr * raz2) / raz2;
        dot *= LN2;
        atomicAdd(&g_loss, -(double)dot / (4.0 * (double)B_HALF));
        __threadfence();
        unsigned done = atomicAdd(&g_done, 1u);
        if (done == (unsigned)(gridDim.x - 1)) {
            __threadfence();
            out[0] = (float)g_loss;
        }
    }
}

// ---------------- launch ----------------
extern "C" void kernel_launch(void* const* d_in, const int* in_sizes, int n_in,
                              void* d_out, int out_size) {
    const float* z = (const float*)d_in[0];
    const float* p = (const float*)d_in[1];
    const float* c = (const float*)d_in[2];
    float* out = (float*)d_out;

    cudaFuncSetAttribute(gemm_dist_imma, cudaFuncAttributeMaxDynamicSharedMemorySize, SMEM_TOTAL);

    normalize_kernel<<<(2 * TWO_B + KC) / 8, 256>>>(z, p, c);
    dim3 ggrid(KC / BN, TWO_B / BM, 2);
    gemm_dist_imma<<<ggrid, 512, SMEM_TOTAL>>>();
    final_kernel<<<B_HALF, 128>>>(out);
}

// round 17
// speedup vs baseline: 1.1990x; 1.1990x over previous
#include <cuda_runtime.h>
#include <cuda_fp16.h>
#include <math.h>
#include <stdint.h>

#define TWO_B 32768
#define B_HALF 16384
#define DIM 256
#define KC 1024
#define BM 128
#define BN 128
#define TOFF2 43.2800875f     // 30 * log2(e)
#define TS2   28.8539008f     // 20 * log2(e)
#define SSH   12.0f
#define LN2   0.6931471805599453f

// ---------------- device scratch (static, no allocation) ----------------
__device__ __align__(16) int8_t g_zq[(size_t)TWO_B * DIM];
__device__ __align__(16) int8_t g_pq[(size_t)TWO_B * DIM];
__device__ __align__(16) int8_t g_cq[(size_t)KC * DIM];
__device__ float g_rsz[TWO_B];
__device__ float g_rsp[TWO_B];
__device__ float g_rsc[KC];
__device__ __align__(16) __half g_tz[(size_t)TWO_B * KC];   // z: E = 2^(t2-TOFF2)
__device__ __align__(16) __half g_tp[(size_t)TWO_B * KC];   // p: t2 (log2 domain)
__device__ float g_cs[4 * KC];
__device__ __align__(16) __half g_ih[2 * KC];               // z: 1024/cs
__device__ __align__(16) __half g_lch[2 * KC];              // p: log2(cs)+TOFF2-SSH
__device__ double g_loss;
__device__ unsigned g_done;

// ---------------- PTX helpers ----------------
__device__ __forceinline__ uint32_t smem_u32(const void* p) {
    uint32_t a;
    asm("{ .reg .u64 t; cvta.to.shared.u64 t, %1; cvt.u32.u64 %0, t; }" : "=r"(a) : "l"(p));
    return a;
}
#define CP_ASYNC16(dst, src) \
    asm volatile("cp.async.cg.shared.global [%0], [%1], 16;" :: "r"(dst), "l"(src) : "memory")
#define CP_COMMIT() asm volatile("cp.async.commit_group;" ::: "memory")
#define CP_WAIT(n)  asm volatile("cp.async.wait_group %0;" :: "n"(n) : "memory")
#define LDSM_X4(r0, r1, r2, r3, addr) \
    asm volatile("ldmatrix.sync.aligned.m8n8.x4.shared.b16 {%0,%1,%2,%3}, [%4];" \
                 : "=r"(r0), "=r"(r1), "=r"(r2), "=r"(r3) : "r"(addr))

__device__ __forceinline__ void mma_s8(int* c, const uint32_t* a, const uint32_t* b) {
    asm volatile(
        "mma.sync.aligned.m16n8k32.row.col.s32.s8.s8.s32 "
        "{%0,%1,%2,%3}, {%4,%5,%6,%7}, {%8,%9}, {%0,%1,%2,%3};"
        : "+r"(c[0]), "+r"(c[1]), "+r"(c[2]), "+r"(c[3])
        : "r"(a[0]), "r"(a[1]), "r"(a[2]), "r"(a[3]), "r"(b[0]), "r"(b[1]));
}

__device__ __forceinline__ __half2 h2ex2(__half2 x) {
    uint32_t xi = *reinterpret_cast<uint32_t*>(&x), ri;
    asm("ex2.approx.f16x2 %0, %1;" : "=r"(ri) : "r"(xi));
    return *reinterpret_cast<__half2*>(&ri);
}
__device__ __forceinline__ float hsum(__half2 h) {
    float2 f = __half22float2(h);
    return f.x + f.y;
}
__device__ __forceinline__ __half2 h2of(uint32_t u) {
    return *reinterpret_cast<__half2*>(&u);
}

__device__ __forceinline__ float dist2f(float sq) {
    return TS2 * sqrtf(fmaxf(sq, 1e-12f));
}

// ---------------- normalize + quantize (+ zero fold-in) ----------------
__device__ __forceinline__ void norm_row_q(const float* __restrict__ src,
                                           int8_t* __restrict__ dstq,
                                           float* __restrict__ rs,
                                           int r, int lane) {
    const float4* s4 = reinterpret_cast<const float4*>(src + (size_t)r * DIM);
    float4 v0 = s4[lane * 2];
    float4 v1 = s4[lane * 2 + 1];
    float ss = v0.x * v0.x + v0.y * v0.y + v0.z * v0.z + v0.w * v0.w
             + v1.x * v1.x + v1.y * v1.y + v1.z * v1.z + v1.w * v1.w;
    #pragma unroll
    for (int o = 16; o > 0; o >>= 1)
        ss += __shfl_xor_sync(0xffffffffu, ss, o);
    float inv = 1.0f / fmaxf(sqrtf(ss), 1e-12f);

    float x[8] = {v0.x * inv, v0.y * inv, v0.z * inv, v0.w * inv,
                  v1.x * inv, v1.y * inv, v1.z * inv, v1.w * inv};
    float m = 0.f;
    #pragma unroll
    for (int j = 0; j < 8; j++) m = fmaxf(m, fabsf(x[j]));
    #pragma unroll
    for (int o = 16; o > 0; o >>= 1)
        m = fmaxf(m, __shfl_xor_sync(0xffffffffu, m, o));

    float s = 127.0f / m;
    int q[8];
    #pragma unroll
    for (int j = 0; j < 8; j++) q[j] = __float2int_rn(x[j] * s);
    uint32_t lo = (q[0] & 0xff) | ((q[1] & 0xff) << 8) | ((q[2] & 0xff) << 16) | ((q[3] & 0xff) << 24);
    uint32_t hi = (q[4] & 0xff) | ((q[5] & 0xff) << 8) | ((q[6] & 0xff) << 16) | ((q[7] & 0xff) << 24);
    *reinterpret_cast<uint2*>(dstq + (size_t)r * DIM + lane * 8) = make_uint2(lo, hi);
    if (lane == 0)
        rs[r] = m * (1.0f / 127.0f);
}

__global__ __launch_bounds__(256) void normalize_kernel(const float* __restrict__ z,
                                                        const float* __restrict__ p,
                                                        const float* __restrict__ c) {
    if (blockIdx.x == 0) {
        int t = threadIdx.x;
        #pragma unroll
        for (int j = 0; j < 16; j++) g_cs[t + j * 256] = 0.0f;
        if (t == 0) { g_loss = 0.0; g_done = 0u; }
    }
    int row = blockIdx.x * 8 + (threadIdx.x >> 5);
    int lane = threadIdx.x & 31;
    if (row < TWO_B)          norm_row_q(z, g_zq, g_rsz, row, lane);
    else if (row < 2 * TWO_B) norm_row_q(p, g_pq, g_rsp, row - TWO_B, lane);
    else                      norm_row_q(c, g_cq, g_rsc, row - 2 * TWO_B, lane);
}

// ---------------- int8 IMMA GEMM + fused distance/exp epilogue ----------------
#define ROWB 272
#define TILE_BYTES (128 * ROWB)
#define SMEM_TOTAL (2 * TILE_BYTES)

__global__ __launch_bounds__(512, 2) void gemm_dist_imma() {
    extern __shared__ char dsm[];
    uint32_t sA = smem_u32(dsm);
    uint32_t sB = sA + TILE_BYTES;

    int tid = threadIdx.x;
    int lane = tid & 31;
    int wid = tid >> 5;
    int wm = wid >> 2;
    int wn = wid & 3;
    int q = lane & 3;
    int gr = lane >> 2;

    int which = blockIdx.z;
    int bm = blockIdx.y;
    int bn = blockIdx.x;

    const int8_t* Ag = (which ? g_pq : g_zq) + (size_t)(bm * BM) * DIM;
    const int8_t* Bg = g_cq + (size_t)(bn * BN) * DIM;
    const float* rsa = which ? g_rsp : g_rsz;
    __half* T = which ? g_tp : g_tz;

    int ltile = tid >> 8;
    int local = tid & 255;
    int lrow = local >> 1;
    int lhalf = local & 1;
    const int8_t* gsrc = (ltile ? Bg : Ag) + (size_t)lrow * DIM + lhalf * 128;
    uint32_t sdst = (ltile ? sB : sA) + lrow * ROWB + lhalf * 128;

    #pragma unroll
    for (int c2 = 0; c2 < 8; c2++)
        CP_ASYNC16(sdst + c2 * 16, gsrc + c2 * 16);
    CP_COMMIT();

    int acc[2][4][4];
    #pragma unroll
    for (int i = 0; i < 2; i++)
        #pragma unroll
        for (int j = 0; j < 4; j++)
            #pragma unroll
            for (int k = 0; k < 4; k++)
                acc[i][j][k] = 0;

    uint32_t aBase = sA + (wm * 32 + (lane & 15)) * ROWB + (lane >> 4) * 16;
    uint32_t bBase = sB + (wn * 32 + (lane & 7) + ((lane >> 4) << 3)) * ROWB
                     + ((lane >> 3) & 1) * 16;

    CP_WAIT(0);
    __syncthreads();

    #pragma unroll
    for (int k32 = 0; k32 < 8; k32++) {
        uint32_t a[2][4], b[2][4];
        #pragma unroll
        for (int mt = 0; mt < 2; mt++)
            LDSM_X4(a[mt][0], a[mt][1], a[mt][2], a[mt][3],
                    aBase + mt * (16 * ROWB) + k32 * 32);
        #pragma unroll
        for (int j = 0; j < 2; j++)
            LDSM_X4(b[j][0], b[j][1], b[j][2], b[j][3],
                    bBase + j * (16 * ROWB) + k32 * 32);
        #pragma unroll
        for (int mt = 0; mt < 2; mt++)
            #pragma unroll
            for (int nt = 0; nt < 4; nt++)
                mma_s8(acc[mt][nt], a[mt], &b[nt >> 1][(nt & 1) * 2]);
    }

    // ---------------- epilogue (na + nc == 2.0 exactly for unit rows) ----------------
    const __half2 toffh = __float2half2_rn(TOFF2);
    float rb0[4], rb1[4];
    #pragma unroll
    for (int nt = 0; nt < 4; nt++) {
        int c = bn * BN + wn * 32 + nt * 8 + 2 * q;
        rb0[nt] = g_rsc[c];
        rb1[nt] = g_rsc[c + 1];
    }

    float es0[4], es1[4];
    #pragma unroll
    for (int nt = 0; nt < 4; nt++) { es0[nt] = 0.f; es1[nt] = 0.f; }

    #pragma unroll
    for (int mt = 0; mt < 2; mt++) {
        int r = bm * BM + wm * 32 + mt * 16 + gr;
        float ra0 = rsa[r], ra1 = rsa[r + 8];
        #pragma unroll
        for (int nt = 0; nt < 4; nt++) {
            int c = bn * BN + wn * 32 + nt * 8 + 2 * q;
            float g00 = (float)acc[mt][nt][0] * (ra0 * rb0[nt]);
            float g01 = (float)acc[mt][nt][1] * (ra0 * rb1[nt]);
            float g10 = (float)acc[mt][nt][2] * (ra1 * rb0[nt]);
            float g11 = (float)acc[mt][nt][3] * (ra1 * rb1[nt]);
            float t00 = dist2f(2.0f - 2.0f * g00);
            float t01 = dist2f(2.0f - 2.0f * g01);
            float t10 = dist2f(2.0f - 2.0f * g10);
            float t11 = dist2f(2.0f - 2.0f * g11);
            __half2 ht0 = __floats2half2_rn(t00, t01);
            __half2 ht1 = __floats2half2_rn(t10, t11);
            __half2 he0 = h2ex2(__hsub2(ht0, toffh));
            __half2 he1 = h2ex2(__hsub2(ht1, toffh));
            *(__half2*)&T[(size_t)r * KC + c]       = which ? ht0 : he0;
            *(__half2*)&T[(size_t)(r + 8) * KC + c] = which ? ht1 : he1;
            float2 f0 = __half22float2(he0);
            float2 f1 = __half22float2(he1);
            es0[nt] += f0.x + f1.x;
            es1[nt] += f0.y + f1.y;
        }
    }

    #pragma unroll
    for (int o = 4; o <= 16; o <<= 1) {
        #pragma unroll
        for (int nt = 0; nt < 4; nt++) {
            es0[nt] += __shfl_xor_sync(0xffffffffu, es0[nt], o);
            es1[nt] += __shfl_xor_sync(0xffffffffu, es1[nt], o);
        }
    }
    if (lane < 4) {
        int csbase = (which * 2 + (bm >> 7)) * KC + bn * BN + wn * 32 + 2 * lane;
        #pragma unroll
        for (int nt = 0; nt < 4; nt++) {
            atomicAdd(&g_cs[csbase + nt * 8], es0[nt]);
            atomicAdd(&g_cs[csbase + nt * 8 + 1], es1[nt]);
        }
    }
}

// ---------------- tail kernels ----------------
__global__ void logcs_kernel() {
    int i = blockIdx.x * blockDim.x + threadIdx.x;
    if (i < 2 * KC)
        g_ih[i] = __float2half(1024.0f / g_cs[i]);
    else if (i < 4 * KC)
        g_lch[i - 2 * KC] = __float2half(log2f(g_cs[i]) + (TOFF2 - SSH));
}

// 128 threads, 8 elements per thread; one block per batch row; last block
// writes the final scalar (finalize merged in).
__global__ __launch_bounds__(128) void final_kernel(float* __restrict__ out) {
    __shared__ float sm[32];
    int b = blockIdx.x;
    int t = threadIdx.x;
    int lane = t & 31;
    int wid = t >> 5;
    int k0 = t * 8;

    uint4 ez1 = *(const uint4*)(g_tz + (size_t)b * KC + k0);
    uint4 ez2 = *(const uint4*)(g_tz + (size_t)(b + B_HALF) * KC + k0);
    uint4 tq1 = *(const uint4*)(g_tp + (size_t)b * KC + k0);
    uint4 tq2 = *(const uint4*)(g_tp + (size_t)(b + B_HALF) * KC + k0);
    uint4 i1u = *(const uint4*)(g_ih + k0);
    uint4 i2u = *(const uint4*)(g_ih + KC + k0);
    uint4 l3u = *(const uint4*)(g_lch + k0);
    uint4 l4u = *(const uint4*)(g_lch + KC + k0);

    const uint32_t* e1w = reinterpret_cast<const uint32_t*>(&ez1);
    const uint32_t* e2w = reinterpret_cast<const uint32_t*>(&ez2);
    const uint32_t* t1w = reinterpret_cast<const uint32_t*>(&tq1);
    const uint32_t* t2w = reinterpret_cast<const uint32_t*>(&tq2);
    const uint32_t* i1w = reinterpret_cast<const uint32_t*>(&i1u);
    const uint32_t* i2w = reinterpret_cast<const uint32_t*>(&i2u);
    const uint32_t* l3w = reinterpret_cast<const uint32_t*>(&l3u);
    const uint32_t* l4w = reinterpret_cast<const uint32_t*>(&l4u);

    __half2 az1h = __float2half2_rn(0.f), az2h = az1h;
    __half2 ap1h = az1h, ap2h = az1h;
    __half2 s1h = az1h, s2h = az1h;

    #pragma unroll
    for (int j = 0; j < 4; j++) {
        __half2 a1 = __hmul2(h2of(e1w[j]), h2of(i1w[j]));
        __half2 a2 = __hmul2(h2of(e2w[j]), h2of(i2w[j]));
        __half2 v1 = __hsub2(h2of(t1w[j]), h2of(l3w[j]));
        __half2 v2 = __hsub2(h2of(t2w[j]), h2of(l4w[j]));
        __half2 p1 = h2ex2(v1);
        __half2 p2 = h2ex2(v2);
        __half2 lp = __hadd2(v1, v2);
        az1h = __hadd2(az1h, a1);
        az2h = __hadd2(az2h, a2);
        ap1h = __hadd2(ap1h, p1);
        ap2h = __hadd2(ap2h, p2);
        s1h = __hfma2(a1, lp, s1h);
        s2h = __hfma2(a2, lp, s2h);
    }

    float az1s = hsum(az1h), az2s = hsum(az2h);
    float ap1s = hsum(ap1h), ap2s = hsum(ap2h);
    float s1 = hsum(s1h), s2 = hsum(s2h);

    #pragma unroll
    for (int o = 16; o > 0; o >>= 1) {
        az1s += __shfl_xor_sync(0xffffffffu, az1s, o);
        az2s += __shfl_xor_sync(0xffffffffu, az2s, o);
        ap1s += __shfl_xor_sync(0xffffffffu, ap1s, o);
        ap2s += __shfl_xor_sync(0xffffffffu, ap2s, o);
        s1   += __shfl_xor_sync(0xffffffffu, s1, o);
        s2   += __shfl_xor_sync(0xffffffffu, s2, o);
    }
    if (lane == 0) {
        sm[wid * 6 + 0] = az1s; sm[wid * 6 + 1] = az2s;
        sm[wid * 6 + 2] = ap1s; sm[wid * 6 + 3] = ap2s;
        sm[wid * 6 + 4] = s1;   sm[wid * 6 + 5] = s2;
    }
    __syncthreads();
    if (t == 0) {
        float raz1 = sm[0] + sm[6] + sm[12] + sm[18];
        float raz2 = sm[1] + sm[7] + sm[13] + sm[19];
        float rap1 = sm[2] + sm[8] + sm[14] + sm[20];
        float rap2 = sm[3] + sm[9] + sm[15] + sm[21];
        float rs1  = sm[4] + sm[10] + sm[16] + sm[22];
        float rs2  = sm[5] + sm[11] + sm[17] + sm[23];
        float lrr = log2f(rap1) + log2f(rap2);
        float dot = (rs1 - lrr * raz1) / raz1 + (rs2 - lrr * raz2) / raz2;
        dot *= LN2;
        atomicAdd(&g_loss, -(double)dot / (4.0 * (double)B_HALF));
        __threadfence();
        unsigned done = atomicAdd(&g_done, 1u);
        if (done == (unsigned)(gridDim.x - 1)) {
            __threadfence();
            out[0] = (float)g_loss;
        }
    }
}

// ---------------- launch ----------------
extern "C" void kernel_launch(void* const* d_in, const int* in_sizes, int n_in,
                              void* d_out, int out_size) {
    const float* z = (const float*)d_in[0];
    const float* p = (const float*)d_in[1];
    const float* c = (const float*)d_in[2];
    float* out = (float*)d_out;

    cudaFuncSetAttribute(gemm_dist_imma, cudaFuncAttributeMaxDynamicSharedMemorySize, SMEM_TOTAL);

    normalize_kernel<<<(2 * TWO_B + KC) / 8, 256>>>(z, p, c);
    dim3 ggrid(KC / BN, TWO_B / BM, 2);
    gemm_dist_imma<<<ggrid, 512, SMEM_TOTAL>>>();
    logcs_kernel<<<16, 256>>>();
    final_kernel<<<B_HALF, 128>>>(out);
}